// round 2
// baseline (speedup 1.0000x reference)
#include <cuda_runtime.h>
#include <cuda_bf16.h>
#include <math.h>

// Problem constants (fixed by the reference)
#define T_TOK 2048          // B*S tokens
#define HDIM  2048
#define FDIM  5504
#define EEXP  8
#define KTOP  2

// GEMM tiling
#define TM 128
#define TN 64
#define TK 16

// ---------------- scratch (static device arrays; no allocation) ----------------
__device__ int   g_cnt[EEXP];
__device__ int   g_pair_tok[EEXP * T_TOK];
__device__ float g_pair_w[EEXP * T_TOK];
// fixed-stride per-expert intermediate: hbuf[(e*T + slot)*F + f]  (~361 MB)
__device__ float g_hbuf[(size_t)EEXP * T_TOK * FDIM];

// ---------------- kernel 0: zero counters ----------------
__global__ void zero_cnt_kernel() {
    if (threadIdx.x < EEXP) g_cnt[threadIdx.x] = 0;
}

// ---------------- kernel 1: router logits + top-2 softmax + bucketing ----------------
// grid = T_TOK blocks, 256 threads (8 warps; warp e computes logit for expert e)
__global__ void __launch_bounds__(256) router_kernel(const float* __restrict__ x,
                                                     const float* __restrict__ rw) {
    int t = blockIdx.x;
    int warp = threadIdx.x >> 5;
    int lane = threadIdx.x & 31;
    __shared__ float logits[EEXP];

    const float* xr = x + (size_t)t * HDIM;
    const float* wr = rw + (size_t)warp * HDIM;
    float s = 0.f;
    for (int h = lane * 4; h < HDIM; h += 32 * 4) {
        float4 xv = *(const float4*)(xr + h);
        float4 wv = *(const float4*)(wr + h);
        s = fmaf(xv.x, wv.x, s);
        s = fmaf(xv.y, wv.y, s);
        s = fmaf(xv.z, wv.z, s);
        s = fmaf(xv.w, wv.w, s);
    }
    #pragma unroll
    for (int o = 16; o; o >>= 1) s += __shfl_down_sync(0xffffffffu, s, o);
    if (lane == 0) logits[warp] = s;
    __syncthreads();

    if (threadIdx.x == 0) {
        // top-1 (ties -> lowest index, matching jax.lax.top_k)
        int i0 = 0; float v0 = logits[0];
        #pragma unroll
        for (int i = 1; i < EEXP; i++) {
            if (logits[i] > v0) { v0 = logits[i]; i0 = i; }
        }
        // top-2
        int i1 = -1; float v1 = -3.0e38f;
        #pragma unroll
        for (int i = 0; i < EEXP; i++) {
            if (i == i0) continue;
            if (logits[i] > v1) { v1 = logits[i]; i1 = i; }
        }
        // softmax over the two selected logits
        float e1 = expf(v1 - v0);
        float inv = 1.f / (1.f + e1);
        float p0 = inv;
        float p1 = e1 * inv;

        int s0 = atomicAdd(&g_cnt[i0], 1);
        g_pair_tok[i0 * T_TOK + s0] = t;
        g_pair_w  [i0 * T_TOK + s0] = p0;
        int s1 = atomicAdd(&g_cnt[i1], 1);
        g_pair_tok[i1 * T_TOK + s1] = t;
        g_pair_w  [i1 * T_TOK + s1] = p1;
    }
}

// ---------------- kernel 2: grouped gate/up GEMM + SiLU ----------------
// grid = (FDIM/TN=86, T_TOK/TM=16, EEXP=8), 256 threads.
// Computes g = Xe @ Wg^T, u = Xe @ Wu^T for this expert's token rows,
// writes silu(g)*u into g_hbuf.
__global__ void __launch_bounds__(256) gateup_kernel(const float* __restrict__ x,
                                                     const float* __restrict__ gw,
                                                     const float* __restrict__ uw) {
    int e = blockIdx.z;
    int cntE = g_cnt[e];
    int m0 = blockIdx.y * TM;
    if (m0 >= cntE) return;
    int n0 = blockIdx.x * TN;

    __shared__ float As[TK][TM];
    __shared__ float Bg[TK][TN];
    __shared__ float Bu[TK][TN];
    __shared__ int   toks[TM];

    int tid = threadIdx.x;
    if (tid < TM) {
        int r = m0 + tid;
        toks[tid] = (r < cntE) ? g_pair_tok[e * T_TOK + r] : -1;
    }
    __syncthreads();

    int tx = tid & 15;       // 0..15 -> 4 cols each
    int ty = tid >> 4;       // 0..15 -> 8 rows each

    float acc_g[8][4];
    float acc_u[8][4];
    #pragma unroll
    for (int i = 0; i < 8; i++)
        #pragma unroll
        for (int j = 0; j < 4; j++) { acc_g[i][j] = 0.f; acc_u[i][j] = 0.f; }

    const float* gwB = gw + ((size_t)e * FDIM + n0) * HDIM;
    const float* uwB = uw + ((size_t)e * FDIM + n0) * HDIM;

    for (int k0 = 0; k0 < HDIM; k0 += TK) {
        // A tile: 128 rows x 16 k = 512 float4 (2 per thread), stored K-major
        #pragma unroll
        for (int i = 0; i < 2; i++) {
            int v = tid + i * 256;
            int row = v >> 2;
            int c4  = v & 3;
            int tok = toks[row];
            float4 val = make_float4(0.f, 0.f, 0.f, 0.f);
            if (tok >= 0) val = *(const float4*)(x + (size_t)tok * HDIM + k0 + c4 * 4);
            As[c4 * 4 + 0][row] = val.x;
            As[c4 * 4 + 1][row] = val.y;
            As[c4 * 4 + 2][row] = val.z;
            As[c4 * 4 + 3][row] = val.w;
        }
        // B tiles: 64 rows x 16 k = 256 float4 each (1 per thread)
        {
            int row = tid >> 2;
            int c4  = tid & 3;
            float4 gv = *(const float4*)(gwB + (size_t)row * HDIM + k0 + c4 * 4);
            Bg[c4 * 4 + 0][row] = gv.x;
            Bg[c4 * 4 + 1][row] = gv.y;
            Bg[c4 * 4 + 2][row] = gv.z;
            Bg[c4 * 4 + 3][row] = gv.w;
            float4 uv = *(const float4*)(uwB + (size_t)row * HDIM + k0 + c4 * 4);
            Bu[c4 * 4 + 0][row] = uv.x;
            Bu[c4 * 4 + 1][row] = uv.y;
            Bu[c4 * 4 + 2][row] = uv.z;
            Bu[c4 * 4 + 3][row] = uv.w;
        }
        __syncthreads();

        #pragma unroll
        for (int kk = 0; kk < TK; kk++) {
            float a[8], bg[4], bu[4];
            *(float4*)&a[0] = *(const float4*)&As[kk][ty * 8];
            *(float4*)&a[4] = *(const float4*)&As[kk][ty * 8 + 4];
            *(float4*)&bg[0] = *(const float4*)&Bg[kk][tx * 4];
            *(float4*)&bu[0] = *(const float4*)&Bu[kk][tx * 4];
            #pragma unroll
            for (int i = 0; i < 8; i++) {
                #pragma unroll
                for (int j = 0; j < 4; j++) {
                    acc_g[i][j] = fmaf(a[i], bg[j], acc_g[i][j]);
                    acc_u[i][j] = fmaf(a[i], bu[j], acc_u[i][j]);
                }
            }
        }
        __syncthreads();
    }

    // epilogue: silu(g)*u -> hbuf
    #pragma unroll
    for (int i = 0; i < 8; i++) {
        int row = m0 + ty * 8 + i;
        if (row < cntE) {
            size_t base = ((size_t)e * T_TOK + row) * FDIM + n0 + tx * 4;
            #pragma unroll
            for (int j = 0; j < 4; j++) {
                float g = acc_g[i][j];
                float u = acc_u[i][j];
                float h = (g / (1.f + expf(-g))) * u;   // silu(g)*u
                g_hbuf[base + j] = h;
            }
        }
    }
}

// ---------------- kernel 3: grouped down GEMM + weighted scatter ----------------
// grid = (HDIM/TN=32, T_TOK/TM=16, EEXP=8), 256 threads.
__global__ void __launch_bounds__(256) down_kernel(const float* __restrict__ dw,
                                                   float* __restrict__ out) {
    int e = blockIdx.z;
    int cntE = g_cnt[e];
    int m0 = blockIdx.y * TM;
    if (m0 >= cntE) return;
    int n0 = blockIdx.x * TN;

    __shared__ float As[TK][TM];
    __shared__ float Bd[TK][TN];

    int tid = threadIdx.x;
    int tx = tid & 15;
    int ty = tid >> 4;

    float acc[8][4];
    #pragma unroll
    for (int i = 0; i < 8; i++)
        #pragma unroll
        for (int j = 0; j < 4; j++) acc[i][j] = 0.f;

    const float* dwB = dw + ((size_t)e * HDIM + n0) * FDIM;
    const float* aB  = g_hbuf + (size_t)(e * T_TOK + m0) * FDIM;

    for (int k0 = 0; k0 < FDIM; k0 += TK) {
        #pragma unroll
        for (int i = 0; i < 2; i++) {
            int v = tid + i * 256;
            int row = v >> 2;
            int c4  = v & 3;
            float4 val = make_float4(0.f, 0.f, 0.f, 0.f);
            if (m0 + row < cntE)
                val = *(const float4*)(aB + (size_t)row * FDIM + k0 + c4 * 4);
            As[c4 * 4 + 0][row] = val.x;
            As[c4 * 4 + 1][row] = val.y;
            As[c4 * 4 + 2][row] = val.z;
            As[c4 * 4 + 3][row] = val.w;
        }
        {
            int row = tid >> 2;
            int c4  = tid & 3;
            float4 dv = *(const float4*)(dwB + (size_t)row * FDIM + k0 + c4 * 4);
            Bd[c4 * 4 + 0][row] = dv.x;
            Bd[c4 * 4 + 1][row] = dv.y;
            Bd[c4 * 4 + 2][row] = dv.z;
            Bd[c4 * 4 + 3][row] = dv.w;
        }
        __syncthreads();

        #pragma unroll
        for (int kk = 0; kk < TK; kk++) {
            float a[8], b[4];
            *(float4*)&a[0] = *(const float4*)&As[kk][ty * 8];
            *(float4*)&a[4] = *(const float4*)&As[kk][ty * 8 + 4];
            *(float4*)&b[0] = *(const float4*)&Bd[kk][tx * 4];
            #pragma unroll
            for (int i = 0; i < 8; i++)
                #pragma unroll
                for (int j = 0; j < 4; j++)
                    acc[i][j] = fmaf(a[i], b[j], acc[i][j]);
        }
        __syncthreads();
    }

    // weighted scatter-add into output (exactly 2 commutative adds per element)
    #pragma unroll
    for (int i = 0; i < 8; i++) {
        int row = m0 + ty * 8 + i;
        if (row < cntE) {
            int tok = g_pair_tok[e * T_TOK + row];
            float w = g_pair_w[e * T_TOK + row];
            float* orow = out + (size_t)tok * HDIM + n0 + tx * 4;
            #pragma unroll
            for (int j = 0; j < 4; j++)
                atomicAdd(&orow[j], acc[i][j] * w);
        }
    }
}

// ---------------- launch ----------------
extern "C" void kernel_launch(void* const* d_in, const int* in_sizes, int n_in,
                              void* d_out, int out_size) {
    const float* x  = (const float*)d_in[0];   // [B,S,H]
    const float* rw = (const float*)d_in[1];   // [E,H]
    const float* gw = (const float*)d_in[2];   // [E,F,H]
    const float* uw = (const float*)d_in[3];   // [E,F,H]
    const float* dw = (const float*)d_in[4];   // [E,H,F]
    float* out = (float*)d_out;                // [B,S,H]

    cudaMemsetAsync(out, 0, (size_t)out_size * sizeof(float));
    zero_cnt_kernel<<<1, 32>>>();
    router_kernel<<<T_TOK, 256>>>(x, rw);
    gateup_kernel<<<dim3(FDIM / TN, T_TOK / TM, EEXP), 256>>>(x, gw, uw);
    down_kernel<<<dim3(HDIM / TN, T_TOK / TM, EEXP), 256>>>(dw, out);
}

// round 4
// speedup vs baseline: 3.0540x; 3.0540x over previous
#include <cuda_runtime.h>
#include <cuda_bf16.h>
#include <cstdint>
#include <math.h>

// ---------------- problem constants ----------------
#define T_TOK 2048
#define HDIM  2048
#define FDIM  5504
#define EEXP  8

// ---------------- device scratch (static, no allocation) ----------------
__device__ int   g_cnt[EEXP];
__device__ int   g_ptok[EEXP * T_TOK];
__device__ float g_pw[EEXP * T_TOK];

#define GAELEM ((size_t)EEXP * (size_t)T_TOK * (size_t)HDIM)
#define HBELEM ((size_t)EEXP * (size_t)T_TOK * (size_t)FDIM)
__device__ __align__(16) __nv_bfloat16 g_gah[GAELEM]; // gathered x hi
__device__ __align__(16) __nv_bfloat16 g_gal[GAELEM]; // gathered x lo
__device__ __align__(16) __nv_bfloat16 g_hbh[HBELEM]; // silu(g)*u hi
__device__ __align__(16) __nv_bfloat16 g_hbl[HBELEM]; // silu(g)*u lo

// ---------------- PTX helpers ----------------
__device__ __forceinline__ uint32_t smem_u32(const void* p) {
    uint32_t a;
    asm("{ .reg .u64 t; cvta.to.shared.u64 t, %1; cvt.u32.u64 %0, t; }"
        : "=r"(a) : "l"(p));
    return a;
}

__device__ __forceinline__ void cpa16(uint32_t dst, const void* src) {
    asm volatile("cp.async.cg.shared.global [%0], [%1], 16;"
                 :: "r"(dst), "l"(src) : "memory");
}
#define CPA_COMMIT() asm volatile("cp.async.commit_group;" ::: "memory")
#define CPA_WAIT1()  asm volatile("cp.async.wait_group 1;" ::: "memory")

__device__ __forceinline__ void ldsm4(uint32_t* r, uint32_t addr) {
    asm volatile("ldmatrix.sync.aligned.m8n8.x4.shared.b16 {%0,%1,%2,%3}, [%4];"
                 : "=r"(r[0]), "=r"(r[1]), "=r"(r[2]), "=r"(r[3]) : "r"(addr));
}

__device__ __forceinline__ void mma16816(float* c, const uint32_t* a, const uint32_t* b) {
    asm volatile(
        "mma.sync.aligned.m16n8k16.row.col.f32.bf16.bf16.f32 "
        "{%0,%1,%2,%3}, {%4,%5,%6,%7}, {%8,%9}, {%0,%1,%2,%3};"
        : "+f"(c[0]), "+f"(c[1]), "+f"(c[2]), "+f"(c[3])
        : "r"(a[0]), "r"(a[1]), "r"(a[2]), "r"(a[3]), "r"(b[0]), "r"(b[1]));
}

// hi/lo split of 4 floats -> bf16 hi/lo pairs
__device__ __forceinline__ void split4(float4 v,
                                       __nv_bfloat16* __restrict__ hi,
                                       __nv_bfloat16* __restrict__ lo,
                                       size_t i) {
    __nv_bfloat162 h0 = __floats2bfloat162_rn(v.x, v.y);
    __nv_bfloat162 h1 = __floats2bfloat162_rn(v.z, v.w);
    *(__nv_bfloat162*)(hi + i)     = h0;
    *(__nv_bfloat162*)(hi + i + 2) = h1;
    __nv_bfloat162 l0, l1;
    l0.x = __float2bfloat16_rn(v.x - __bfloat162float(h0.x));
    l0.y = __float2bfloat16_rn(v.y - __bfloat162float(h0.y));
    l1.x = __float2bfloat16_rn(v.z - __bfloat162float(h1.x));
    l1.y = __float2bfloat16_rn(v.w - __bfloat162float(h1.y));
    *(__nv_bfloat162*)(lo + i)     = l0;
    *(__nv_bfloat162*)(lo + i + 2) = l1;
}

// ---------------- kernel 0: zero counters ----------------
__global__ void zero_cnt_kernel() {
    if (threadIdx.x < EEXP) g_cnt[threadIdx.x] = 0;
}

// ---------------- kernel 1: router ----------------
__global__ void __launch_bounds__(256) router_kernel(const float* __restrict__ x,
                                                     const float* __restrict__ rw) {
    int t = blockIdx.x;
    int warp = threadIdx.x >> 5;
    int lane = threadIdx.x & 31;
    __shared__ float logits[EEXP];

    const float* xr = x + (size_t)t * HDIM;
    const float* wr = rw + (size_t)warp * HDIM;
    float s = 0.f;
    for (int h = lane * 4; h < HDIM; h += 128) {
        float4 xv = *(const float4*)(xr + h);
        float4 wv = *(const float4*)(wr + h);
        s = fmaf(xv.x, wv.x, s);
        s = fmaf(xv.y, wv.y, s);
        s = fmaf(xv.z, wv.z, s);
        s = fmaf(xv.w, wv.w, s);
    }
    #pragma unroll
    for (int o = 16; o; o >>= 1) s += __shfl_down_sync(0xffffffffu, s, o);
    if (lane == 0) logits[warp] = s;
    __syncthreads();

    if (threadIdx.x == 0) {
        int i0 = 0; float v0 = logits[0];
        #pragma unroll
        for (int i = 1; i < EEXP; i++)
            if (logits[i] > v0) { v0 = logits[i]; i0 = i; }
        int i1 = -1; float v1 = -3.0e38f;
        #pragma unroll
        for (int i = 0; i < EEXP; i++) {
            if (i == i0) continue;
            if (logits[i] > v1) { v1 = logits[i]; i1 = i; }
        }
        float e1 = expf(v1 - v0);
        float inv = 1.f / (1.f + e1);
        int s0 = atomicAdd(&g_cnt[i0], 1);
        g_ptok[i0 * T_TOK + s0] = t;
        g_pw  [i0 * T_TOK + s0] = inv;
        int s1 = atomicAdd(&g_cnt[i1], 1);
        g_ptok[i1 * T_TOK + s1] = t;
        g_pw  [i1 * T_TOK + s1] = e1 * inv;
    }
}

// ---------------- kernel 2: gather tokens + bf16 hi/lo split ----------------
__global__ void __launch_bounds__(128) gather_x_kernel(const float* __restrict__ x) {
    int row = blockIdx.x;                 // e*T_TOK + slot
    int e = row >> 11;
    int slot = row & (T_TOK - 1);
    if (slot >= g_cnt[e]) return;
    const float4* src = (const float4*)(x + (size_t)g_ptok[row] * HDIM);
    size_t ob = (size_t)row * HDIM;
    for (int i = threadIdx.x; i < HDIM / 4; i += 128)
        split4(src[i], g_gah, g_gal, ob + (size_t)i * 4);
}

// ---------------- shared GEMM machinery ----------------
// smem: A buffers (hi 16K | lo 16K) x2, B buffers (hi 16K | lo 16K) x2 = 128KB
#define SA0 0u
#define SA1 32768u
#define SB0 65536u
#define SB1 98304u
#define SMEM_GEMM 131072

// cp.async a 128x64 bf16 hi/lo A tile into SW128-swizzled smem
__device__ __forceinline__ void cpa_tileA(uint32_t base,
                                          const __nv_bfloat16* __restrict__ hi,
                                          const __nv_bfloat16* __restrict__ lo,
                                          size_t stride, int k0, int tid) {
    #pragma unroll
    for (int i = 0; i < 4; i++) {
        int flat = tid + (i << 8);
        int r = flat >> 3, u = flat & 7;
        uint32_t dst = base + r * 128 + ((u ^ (r & 7)) << 4);
        size_t off = (size_t)r * stride + k0 + u * 8;
        cpa16(dst, hi + off);
        cpa16(dst + 16384, lo + off);
    }
}

// store fp32 regs as bf16 hi/lo into swizzled B tile (optionally interleaving
// gate/up rows: smem row = 2*r (gate) / 2*r+1 (up))
template <bool IL>
__device__ __forceinline__ void sts_B(char* sm, uint32_t sboff, const float4* br, int tid) {
    #pragma unroll
    for (int i = 0; i < 8; i++) {
        int flat = tid + (i << 8);
        int row = flat >> 4, c4 = flat & 15;
        int sr = IL ? ((row < 64) ? (row << 1) : (((row - 64) << 1) + 1)) : row;
        uint32_t off = sboff + sr * 128 + (((c4 >> 1) ^ (sr & 7)) << 4) + ((c4 & 1) << 3);
        float4 v = br[i];
        __nv_bfloat162 h0 = __floats2bfloat162_rn(v.x, v.y);
        __nv_bfloat162 h1 = __floats2bfloat162_rn(v.z, v.w);
        *(__nv_bfloat162*)(sm + off)     = h0;
        *(__nv_bfloat162*)(sm + off + 4) = h1;
        __nv_bfloat162 l0, l1;
        l0.x = __float2bfloat16_rn(v.x - __bfloat162float(h0.x));
        l0.y = __float2bfloat16_rn(v.y - __bfloat162float(h0.y));
        l1.x = __float2bfloat16_rn(v.z - __bfloat162float(h1.x));
        l1.y = __float2bfloat16_rn(v.w - __bfloat162float(h1.y));
        *(__nv_bfloat162*)(sm + off + 16384)     = l0;
        *(__nv_bfloat162*)(sm + off + 16384 + 4) = l1;
    }
}

// two k16 steps of the 3-pass bf16x3 MMA over a 64x32 warp tile
__device__ __forceinline__ void mma_half(uint32_t Ab, uint32_t Bb, int kk0,
                                         int wm, int wn, int lane,
                                         float (&acc)[4][4][4]) {
    #pragma unroll
    for (int ks = 0; ks < 2; ks++) {
        int kk = kk0 + ks * 16;
        uint32_t ah[4][4], al[4][4], bh[4][2], bl[4][2];
        int lrow = lane & 15;
        int au = (kk >> 3) + (lane >> 4);          // A smem unit
        #pragma unroll
        for (int mi = 0; mi < 4; mi++) {
            int r = wm * 64 + mi * 16 + lrow;
            uint32_t ad = Ab + r * 128 + ((au ^ (r & 7)) << 4);
            ldsm4(ah[mi], ad);
            ldsm4(al[mi], ad + 16384);
        }
        int bu = (kk >> 3) + ((lane >> 3) & 1);    // B smem unit
        #pragma unroll
        for (int bi = 0; bi < 2; bi++) {
            int nr = wn * 32 + bi * 16 + ((lane >> 4) << 3) + (lane & 7);
            uint32_t bd = Bb + nr * 128 + ((bu ^ (nr & 7)) << 4);
            uint32_t t[4];
            ldsm4(t, bd);
            bh[2 * bi][0] = t[0]; bh[2 * bi][1] = t[1];
            bh[2 * bi + 1][0] = t[2]; bh[2 * bi + 1][1] = t[3];
            ldsm4(t, bd + 16384);
            bl[2 * bi][0] = t[0]; bl[2 * bi][1] = t[1];
            bl[2 * bi + 1][0] = t[2]; bl[2 * bi + 1][1] = t[3];
        }
        #pragma unroll
        for (int mi = 0; mi < 4; mi++)
            #pragma unroll
            for (int ni = 0; ni < 4; ni++) {
                mma16816(acc[mi][ni], ah[mi], bh[ni]);
                mma16816(acc[mi][ni], al[mi], bh[ni]);
                mma16816(acc[mi][ni], ah[mi], bl[ni]);
            }
    }
}

// ---------------- kernel 3: gate/up GEMM (HMMA bf16x3) + SiLU ----------------
// grid (16 mtiles, 86 ftiles, 8 experts), 256 threads, C = 128x128 (64 f-cols interleaved g/u)
__global__ void __launch_bounds__(256, 1) gemm1_kernel(const float* __restrict__ gw,
                                                       const float* __restrict__ uw) {
    extern __shared__ char sm[];
    uint32_t sb = smem_u32(sm);
    int e = blockIdx.z;
    int cnt = g_cnt[e];
    int m0 = blockIdx.x << 7;
    if (m0 >= cnt) return;
    int n0f = blockIdx.y << 6;
    int tid = threadIdx.x, lane = tid & 31, wid = tid >> 5;
    int wm = wid & 1, wn = wid >> 1;

    const __nv_bfloat16* Ahi = g_gah + ((size_t)e * T_TOK + m0) * HDIM;
    const __nv_bfloat16* Alo = g_gal + ((size_t)e * T_TOK + m0) * HDIM;
    const float* gwB = gw + ((size_t)e * FDIM + n0f) * HDIM;
    const float* uwB = uw + ((size_t)e * FDIM + n0f) * HDIM;

    float acc[4][4][4];
    #pragma unroll
    for (int a = 0; a < 4; a++)
        #pragma unroll
        for (int b = 0; b < 4; b++)
            #pragma unroll
            for (int c = 0; c < 4; c++) acc[a][b][c] = 0.f;

    float4 br[8];
    const int NC = HDIM / 64;   // 32

    // prologue
    cpa_tileA(sb + SA0, Ahi, Alo, HDIM, 0, tid);
    CPA_COMMIT();
    #pragma unroll
    for (int i = 0; i < 8; i++) {
        int flat = tid + (i << 8);
        int row = flat >> 4, c4 = flat & 15;
        const float* s = (row < 64) ? (gwB + (size_t)row * HDIM)
                                    : (uwB + (size_t)(row - 64) * HDIM);
        br[i] = *(const float4*)(s + c4 * 4);
    }
    cpa_tileA(sb + SA1, Ahi, Alo, HDIM, 64, tid);
    CPA_COMMIT();
    sts_B<true>(sm, SB0, br, tid);
    #pragma unroll
    for (int i = 0; i < 8; i++) {
        int flat = tid + (i << 8);
        int row = flat >> 4, c4 = flat & 15;
        const float* s = (row < 64) ? (gwB + (size_t)row * HDIM)
                                    : (uwB + (size_t)(row - 64) * HDIM);
        br[i] = *(const float4*)(s + 64 + c4 * 4);
    }
    CPA_WAIT1();
    __syncthreads();

    for (int c = 0; c < NC; c++) {
        uint32_t Ab = sb + ((c & 1) ? SA1 : SA0);
        uint32_t Bb = sb + ((c & 1) ? SB1 : SB0);
        mma_half(Ab, Bb, 0, wm, wn, lane, acc);
        if (c + 1 < NC) sts_B<true>(sm, (c & 1) ? SB0 : SB1, br, tid);
        mma_half(Ab, Bb, 32, wm, wn, lane, acc);
        __syncthreads();
        if (c + 2 < NC)
            cpa_tileA(sb + ((c & 1) ? SA1 : SA0), Ahi, Alo, HDIM, (c + 2) * 64, tid);
        CPA_COMMIT();
        if (c + 2 < NC) {
            int k0 = (c + 2) * 64;
            #pragma unroll
            for (int i = 0; i < 8; i++) {
                int flat = tid + (i << 8);
                int row = flat >> 4, c4 = flat & 15;
                const float* s = (row < 64) ? (gwB + (size_t)row * HDIM)
                                            : (uwB + (size_t)(row - 64) * HDIM);
                br[i] = *(const float4*)(s + k0 + c4 * 4);
            }
        }
        CPA_WAIT1();
        __syncthreads();
    }

    // epilogue: cols 2j/2j+1 = (gate_j, up_j); h = silu(g)*u -> hi/lo bf16
    #pragma unroll
    for (int mi = 0; mi < 4; mi++)
        #pragma unroll
        for (int rh = 0; rh < 2; rh++) {
            int row = wm * 64 + mi * 16 + (lane >> 2) + rh * 8;
            int slot = m0 + row;
            if (slot < cnt) {
                size_t hb = ((size_t)e * T_TOK + slot) * FDIM + n0f;
                #pragma unroll
                for (int ni = 0; ni < 4; ni++) {
                    float g = acc[mi][ni][rh * 2 + 0];
                    float u = acc[mi][ni][rh * 2 + 1];
                    float h = u * g / (1.f + __expf(-g));
                    int j = wn * 16 + ni * 4 + (lane & 3);
                    __nv_bfloat16 hh = __float2bfloat16_rn(h);
                    g_hbh[hb + j] = hh;
                    g_hbl[hb + j] = __float2bfloat16_rn(h - __bfloat162float(hh));
                }
            }
        }
}

// ---------------- kernel 4: down GEMM (HMMA bf16x3) + weighted scatter ----------------
// grid (16 mtiles, 16 htiles, 8 experts), 256 threads, C = 128x128
__global__ void __launch_bounds__(256, 1) gemm2_kernel(const float* __restrict__ dw,
                                                       float* __restrict__ out) {
    extern __shared__ char sm[];
    uint32_t sb = smem_u32(sm);
    int e = blockIdx.z;
    int cnt = g_cnt[e];
    int m0 = blockIdx.x << 7;
    if (m0 >= cnt) return;
    int n0 = blockIdx.y << 7;
    int tid = threadIdx.x, lane = tid & 31, wid = tid >> 5;
    int wm = wid & 1, wn = wid >> 1;

    const __nv_bfloat16* Ahi = g_hbh + ((size_t)e * T_TOK + m0) * FDIM;
    const __nv_bfloat16* Alo = g_hbl + ((size_t)e * T_TOK + m0) * FDIM;
    const float* dwB = dw + ((size_t)e * HDIM + n0) * FDIM;

    float acc[4][4][4];
    #pragma unroll
    for (int a = 0; a < 4; a++)
        #pragma unroll
        for (int b = 0; b < 4; b++)
            #pragma unroll
            for (int c = 0; c < 4; c++) acc[a][b][c] = 0.f;

    float4 br[8];
    const int NC = FDIM / 64;   // 86

    cpa_tileA(sb + SA0, Ahi, Alo, FDIM, 0, tid);
    CPA_COMMIT();
    #pragma unroll
    for (int i = 0; i < 8; i++) {
        int flat = tid + (i << 8);
        int row = flat >> 4, c4 = flat & 15;
        br[i] = *(const float4*)(dwB + (size_t)row * FDIM + c4 * 4);
    }
    cpa_tileA(sb + SA1, Ahi, Alo, FDIM, 64, tid);
    CPA_COMMIT();
    sts_B<false>(sm, SB0, br, tid);
    #pragma unroll
    for (int i = 0; i < 8; i++) {
        int flat = tid + (i << 8);
        int row = flat >> 4, c4 = flat & 15;
        br[i] = *(const float4*)(dwB + (size_t)row * FDIM + 64 + c4 * 4);
    }
    CPA_WAIT1();
    __syncthreads();

    for (int c = 0; c < NC; c++) {
        uint32_t Ab = sb + ((c & 1) ? SA1 : SA0);
        uint32_t Bb = sb + ((c & 1) ? SB1 : SB0);
        mma_half(Ab, Bb, 0, wm, wn, lane, acc);
        if (c + 1 < NC) sts_B<false>(sm, (c & 1) ? SB0 : SB1, br, tid);
        mma_half(Ab, Bb, 32, wm, wn, lane, acc);
        __syncthreads();
        if (c + 2 < NC)
            cpa_tileA(sb + ((c & 1) ? SA1 : SA0), Ahi, Alo, FDIM, (c + 2) * 64, tid);
        CPA_COMMIT();
        if (c + 2 < NC) {
            int k0 = (c + 2) * 64;
            #pragma unroll
            for (int i = 0; i < 8; i++) {
                int flat = tid + (i << 8);
                int row = flat >> 4, c4 = flat & 15;
                br[i] = *(const float4*)(dwB + (size_t)row * FDIM + k0 + c4 * 4);
            }
        }
        CPA_WAIT1();
        __syncthreads();
    }

    // epilogue: weighted atomic scatter to out
    #pragma unroll
    for (int mi = 0; mi < 4; mi++)
        #pragma unroll
        for (int rh = 0; rh < 2; rh++) {
            int row = wm * 64 + mi * 16 + (lane >> 2) + rh * 8;
            int slot = m0 + row;
            if (slot < cnt) {
                int tok = g_ptok[e * T_TOK + slot];
                float w = g_pw[e * T_TOK + slot];
                float* orow = out + (size_t)tok * HDIM + n0;
                #pragma unroll
                for (int ni = 0; ni < 4; ni++) {
                    int col = wn * 32 + ni * 8 + 2 * (lane & 3);
                    atomicAdd(orow + col,     acc[mi][ni][rh * 2 + 0] * w);
                    atomicAdd(orow + col + 1, acc[mi][ni][rh * 2 + 1] * w);
                }
            }
        }
}

// ---------------- launch ----------------
extern "C" void kernel_launch(void* const* d_in, const int* in_sizes, int n_in,
                              void* d_out, int out_size) {
    const float* x  = (const float*)d_in[0];   // [B,S,H]
    const float* rw = (const float*)d_in[1];   // [E,H]
    const float* gw = (const float*)d_in[2];   // [E,F,H]
    const float* uw = (const float*)d_in[3];   // [E,F,H]
    const float* dw = (const float*)d_in[4];   // [E,H,F]
    float* out = (float*)d_out;

    // idempotent attribute opt-in (not a stream op)
    cudaFuncSetAttribute(gemm1_kernel, cudaFuncAttributeMaxDynamicSharedMemorySize, SMEM_GEMM);
    cudaFuncSetAttribute(gemm2_kernel, cudaFuncAttributeMaxDynamicSharedMemorySize, SMEM_GEMM);

    cudaMemsetAsync(out, 0, (size_t)out_size * sizeof(float));
    zero_cnt_kernel<<<1, 32>>>();
    router_kernel<<<T_TOK, 256>>>(x, rw);
    gather_x_kernel<<<EEXP * T_TOK, 128>>>(x);
    gemm1_kernel<<<dim3(16, FDIM / 64, EEXP), 256, SMEM_GEMM>>>(gw, uw);
    gemm2_kernel<<<dim3(16, HDIM / 128, EEXP), 256, SMEM_GEMM>>>(dw, out);
}